// round 8
// baseline (speedup 1.0000x reference)
#include <cuda_runtime.h>

// Skip-gram negative-sampling loss, fully fused (single kernel).
// Inputs (metadata order): pos_u [B] i32, pos_v [B] i32, neg_v [B,10] i32,
//                          u_weight [V,128] f32, v_weight [V,128] f32
// Output: scalar f32 = mean_b( softplus(-clip(u.v)) - sum_n softplus(u.neg_n) )

#define DIM   128
#define NNEG  10
#define MAX_PARTIALS 16384

__device__ float        g_partials[MAX_PARTIALS];
__device__ unsigned int g_ticket = 0;   // atomicInc wraps at grid-1 -> self-resetting

__device__ __forceinline__ float softplusf(float x) {
    // log(1 + e^x); fast-math variant, |rel err| ~1e-6 at our magnitudes
    return x > 0.0f ? x + __logf(1.0f + __expf(-x))
                    : __logf(1.0f + __expf(x));
}

__global__ void __launch_bounds__(256)
skipgram_fused(const int* __restrict__ pos_u,
               const int* __restrict__ pos_v,
               const int* __restrict__ neg_v,
               const float4* __restrict__ uw,   // [V, 32] float4
               const float4* __restrict__ vw,   // [V, 32] float4
               float* __restrict__ out,
               int batch, float inv_batch)
{
    const int lane = threadIdx.x & 31;
    const int warp = threadIdx.x >> 5;
    const int b = blockIdx.x * (blockDim.x >> 5) + warp;

    __shared__ float s_warp[8];
    __shared__ bool  s_last;

    float loss = 0.0f;
    if (b < batch) {
        const int iu = __ldg(pos_u + b);
        const int iv = __ldg(pos_v + b);

        // Lane-parallel index load: lanes 0..9 fetch the 10 neg indices in
        // one coalesced transaction; shuffles (not L2 round-trips) feed the
        // gather addresses.
        int my_neg = 0;
        if (lane < NNEG) my_neg = __ldg(neg_v + (size_t)b * NNEG + lane);

        // Each lane owns 4 consecutive floats of the 128-dim row.
        const float4 u = uw[(size_t)iu * 32 + lane];
        const float4 v = vw[(size_t)iv * 32 + lane];

        float acc[NNEG + 1];
        acc[0] = u.x * v.x + u.y * v.y + u.z * v.z + u.w * v.w;

        #pragma unroll
        for (int n = 0; n < NNEG; n++) {
            const int in_ = __shfl_sync(0xffffffffu, my_neg, n);
            const float4 w = vw[(size_t)in_ * 32 + lane];
            acc[n + 1] = u.x * w.x + u.y * w.y + u.z * w.z + u.w * w.w;
        }

        // Butterfly-reduce all 11 dots; independent accumulators pipeline.
        #pragma unroll
        for (int n = 0; n < NNEG + 1; n++) {
            float a = acc[n];
            a += __shfl_xor_sync(0xffffffffu, a, 16);
            a += __shfl_xor_sync(0xffffffffu, a, 8);
            a += __shfl_xor_sync(0xffffffffu, a, 4);
            a += __shfl_xor_sync(0xffffffffu, a, 2);
            a += __shfl_xor_sync(0xffffffffu, a, 1);
            acc[n] = a;
        }

        const float sc = fminf(fmaxf(acc[0], -10.0f), 10.0f);
        loss = softplusf(-sc);                 // -log_sigmoid(score)
        #pragma unroll
        for (int n = 1; n <= NNEG; n++)
            loss -= softplusf(acc[n]);         // + log_sigmoid(-neg_dot)
    }

    // Deterministic block reduction (fixed order).
    if (lane == 0) s_warp[warp] = loss;
    __syncthreads();
    if (threadIdx.x == 0) {
        float p = 0.0f;
        #pragma unroll
        for (int i = 0; i < 8; i++) p += s_warp[i];
        g_partials[blockIdx.x] = p;
        __threadfence();
        // atomicInc with limit grid-1: the last block's inc wraps the ticket
        // back to 0, so state is clean for the next graph replay.
        unsigned t = atomicInc(&g_ticket, gridDim.x - 1);
        s_last = (t == gridDim.x - 1);
    }
    __syncthreads();

    // Last block performs the final reduction — fixed iteration order over
    // g_partials, so the scalar output is bit-deterministic.
    if (s_last) {
        __threadfence();
        float p = 0.0f;
        for (int i = threadIdx.x; i < gridDim.x; i += 256)
            p += g_partials[i];
        __shared__ float s_red[256];
        s_red[threadIdx.x] = p;
        __syncthreads();
        #pragma unroll
        for (int off = 128; off > 0; off >>= 1) {
            if (threadIdx.x < off) s_red[threadIdx.x] += s_red[threadIdx.x + off];
            __syncthreads();
        }
        if (threadIdx.x == 0) *out = s_red[0] * inv_batch;
    }
}

extern "C" void kernel_launch(void* const* d_in, const int* in_sizes, int n_in,
                              void* d_out, int out_size)
{
    const int*    pos_u = (const int*)d_in[0];
    const int*    pos_v = (const int*)d_in[1];
    const int*    neg_v = (const int*)d_in[2];
    const float4* uw    = (const float4*)d_in[3];
    const float4* vw    = (const float4*)d_in[4];

    const int batch = in_sizes[0];
    const int threads = 256;
    const int wpb = threads / 32;
    const int blocks = (batch + wpb - 1) / wpb;   // 8192 for B=65536

    skipgram_fused<<<blocks, threads>>>(pos_u, pos_v, neg_v, uw, vw,
                                        (float*)d_out, batch,
                                        1.0f / (float)batch);
}